// round 14
// baseline (speedup 1.0000x reference)
#include <cuda_runtime.h>
#include <cuda_bf16.h>
#include <cstdint>

// LengthRegulator, single launch, per-slice distributed producers:
//   x (32,512,384) f32, duration (32,512) int64/int32 (runtime-detected), max_len=4096
//   out = (32,4096,384) f32 + mel_len tail (layout inferred from out_size).
//
// Grid = 8192 blocks of (96,4); block n expands output rows [16n, 16n+16).
// Blocks with (n % 32 == 0) are ALSO producers: they scan their batch's 512
// durations (redundant per producer, ~600 cyc) and inverse-scatter the 512-
// position g_idx slice containing their rows, then release flag[batch][slice].
// Consumers poll only their slice's flag; producer index floor(n/32)*32 <= n
// guarantees the producer is resident no later than any of its consumers.

#define B_    32
#define T_    512
#define C_    384
#define ML_   4096
#define C4_   (C_ / 4)            // 96 float4 per row
#define RPB   16                  // rows per block
#define UNR   4                   // rows per thread
#define NTHR  (C4_ * 4)           // 384 threads
#define SLC   512                 // output rows per slice
#define NSLC  (B_ * ML_ / SLC)    // 256 slices
#define CPS   (SLC / RPB)         // 32 consumer blocks per slice
#define GRID  ((B_ * ML_) / RPB)  // 8192 blocks

__device__ int g_idx[B_ * ML_];   // input-row index per output row; -1 = masked
__device__ int g_flag[NSLC];      // per-slice ready flags (self-resetting)
__device__ unsigned int g_done;   // completion counter (self-resetting)

__global__ void __launch_bounds__(NTHR) lr_fused_kernel(const float4* __restrict__ x,
                                                        const void* __restrict__ dur_raw,
                                                        float* __restrict__ out,
                                                        int mel_mode) {
    __shared__ int s_csum[T_];
    __shared__ int s_wsum[16];

    const int c4  = threadIdx.x;              // 0..95
    const int ty  = threadIdx.y;              // 0..3
    const int tid = ty * C4_ + c4;            // 0..383

    const int rowBase = blockIdx.x * RPB;     // first output row (global)
    const int b       = rowBase >> 12;        // batch
    const int slice   = rowBase >> 9;         // global slice id (= flag index)
    const bool isProd = ((blockIdx.x & (CPS - 1)) == 0);

    if (isProd) {
        // ================= PRODUCER: scan batch b, scatter slice =================
        const int lane = tid & 31;
        const int wid  = tid >> 5;            // 0..11

        // int64 vs int32: odd int32 words of first 512 elements all zero => int64
        int pred = 0;
        for (int i = tid; i < T_; i += NTHR)
            pred |= ((const int*)dur_raw)[2 * i + 1];
        const int is32 = __syncthreads_or(pred != 0);

        for (int i = tid; i < T_; i += NTHR) {
            long long dv;
            if (is32) dv = (long long)((const int*)dur_raw)[(size_t)b * T_ + i];
            else      dv = ((const long long*)dur_raw)[(size_t)b * T_ + i];
            s_csum[i] = dv > 0 ? (int)dv : 0;
        }
        __syncthreads();

        // inclusive scan: 16 chunks of 32, warps 0..11 sweep chunks
        for (int chunk = wid; chunk < 16; chunk += 12) {
            int v = s_csum[chunk * 32 + lane];
            #pragma unroll
            for (int off = 1; off < 32; off <<= 1) {
                int n = __shfl_up_sync(0xffffffffu, v, off);
                if (lane >= off) v += n;
            }
            s_csum[chunk * 32 + lane] = v;
            if (lane == 31) s_wsum[chunk] = v;
        }
        __syncthreads();
        if (wid == 0) {
            int wv = (lane < 16) ? s_wsum[lane] : 0;
            #pragma unroll
            for (int off = 1; off < 16; off <<= 1) {
                int n = __shfl_up_sync(0xffffffffu, wv, off);
                if (lane >= off) wv += n;
            }
            if (lane < 16) s_wsum[lane] = wv;
        }
        __syncthreads();
        for (int i = tid; i < T_; i += NTHR)
            if (i >= 32) s_csum[i] += s_wsum[(i >> 5) - 1];
        __syncthreads();

        const int mel = s_csum[T_ - 1];

        // mel tail: slice-0 producer of each batch
        const int p0 = (slice & 7) * SLC;     // slice start within batch
        if (p0 == 0 && tid == 0) {
            const size_t total = (size_t)B_ * ML_ * C_;
            if (mel_mode == 1)      out[total + b] = (float)mel;
            else if (mel_mode == 2) ((long long*)(out + total))[b] = (long long)mel;
        }

        // inverse scatter restricted to [p0, p0+SLC)
        const int p1 = p0 + SLC;
        int* gb = g_idx + b * ML_;
        for (int i = tid; i < T_; i += NTHR) {
            int start = (i == 0) ? 0 : s_csum[i - 1];
            int end   = s_csum[i];
            if (start < p0) start = p0;
            if (end   > p1) end   = p1;
            for (int p = start; p < end; ++p) gb[p] = i;
        }
        int mstart = mel > p0 ? mel : p0;     // masked tail within slice
        for (int p = mstart + tid; p < p1; p += NTHR) gb[p] = -1;

        __threadfence();                      // publish g_idx before flag
        __syncthreads();
        if (tid == 0) atomicExch(&g_flag[slice], 1);
    } else {
        // ================= CONSUMER: wait for this slice's flag =================
        if (tid == 0) {
            while (atomicAdd(&g_flag[slice], 0) == 0) __nanosleep(32);
            __threadfence();                  // acquire
        }
        __syncthreads();
    }

    // ================= EXPAND: proven DRAM-floor body =================
    const int row0 = rowBase + ty;            // rows: row0 + 4*k

    int idx[UNR];
    #pragma unroll
    for (int k = 0; k < UNR; ++k)
        idx[k] = __ldcg(&g_idx[row0 + 4 * k]);            // warp-uniform, L2

    const float4* xb = x + (size_t)b * T_ * C4_;
    float4 v[UNR];
    #pragma unroll
    for (int k = 0; k < UNR; ++k) {
        if (idx[k] >= 0) v[k] = __ldg(&xb[(size_t)idx[k] * C4_ + c4]);
        else             v[k] = make_float4(0.f, 0.f, 0.f, 0.f);
    }

    float4* out4 = (float4*)out;
    #pragma unroll
    for (int k = 0; k < UNR; ++k)
        out4[(size_t)(row0 + 4 * k) * C4_ + c4] = v[k];   // coalesced 1536 B/row

    // ================= RESET flags (last block) for deterministic replay ======
    __syncthreads();
    if (tid == 0) {
        if (atomicAdd(&g_done, 1u) == (unsigned)(GRID - 1)) {
            for (int f = 0; f < NSLC; ++f) g_flag[f] = 0;
            __threadfence();
            g_done = 0u;
        }
    }
}

// ---------------------------------------------------------------------------
extern "C" void kernel_launch(void* const* d_in, const int* in_sizes, int n_in,
                              void* d_out, int out_size) {
    const float* x   = (const float*)d_in[0];
    const void*  dur = d_in[1];
    float* out = (float*)d_out;

    const long long total = (long long)B_ * ML_ * C_;
    const long long extra = (long long)out_size - total;
    int mel_mode = 0;
    if (extra == B_)          mel_mode = 1;   // float32 tail
    else if (extra == 2 * B_) mel_mode = 2;   // raw int64 tail

    dim3 blk(C4_, 4);
    lr_fused_kernel<<<GRID, blk>>>((const float4*)x, dur, out, mel_mode);
}

// round 15
// speedup vs baseline: 1.7708x; 1.7708x over previous
#include <cuda_runtime.h>
#include <cuda_bf16.h>
#include <cstdint>

// LengthRegulator, two-kernel:
//   x (32,512,384) f32, duration (32,512) int64/int32 (runtime-detected), max_len=4096
//   out = (32,4096,384) f32 + mel_len tail (layout inferred from out_size).
//
// K1 (256 blocks, 8/batch): redundant per-block shuffle scan + inverse-scatter
//     of a 512-position g_idx slice (~1.5us).
// K2 (4096 blocks): MLP-8 expand with bounded regs: 8 idx upfront, then two
//     groups of {4 gathers -> 4 coalesced stores}. Stores are fire-and-forget,
//     so ~8 loads are in flight while only 4 float4 stay live (regs ~40,
//     4 CTAs/SM) — attacks the measured latency gap (DRAM 58%, issue 17%).

#define B_   32
#define T_   512
#define C_   384
#define ML_  4096
#define C4_  (C_ / 4)            // 96 float4 per row
#define RPB  32                  // rows per expand block
#define NTHR (C4_ * 4)           // 384 threads
#define SPB  8                   // scan blocks per batch
#define SLC  (ML_ / SPB)         // 512 output positions per scan block

__device__ int g_idx[B_ * ML_];  // input-row index per output row; -1 = masked

// ---------------------------------------------------------------------------
// Kernel 1: grid = B_*SPB = 256, block = T_ (512 threads).
// Each block: scan batch durations, inverse-scatter its g_idx slice.
// ---------------------------------------------------------------------------
__global__ void __launch_bounds__(T_) lr_scan_kernel(const void* __restrict__ dur_raw,
                                                     float* __restrict__ out,
                                                     int mel_mode) {
    __shared__ int s_csum[T_];
    __shared__ int s_wsum[16];

    const int t    = threadIdx.x;
    const int b    = blockIdx.x >> 3;           // batch
    const int s    = blockIdx.x & (SPB - 1);    // slice within batch
    const int lane = t & 31;
    const int wid  = t >> 5;

    // int64 vs int32: odd int32 words of first 512 elements all zero => int64
    int pred = ((const int*)dur_raw)[2 * t + 1];
    const int is32 = __syncthreads_or(pred != 0);

    long long dv;
    if (is32) dv = (long long)((const int*)dur_raw)[(size_t)b * T_ + t];
    else      dv = ((const long long*)dur_raw)[(size_t)b * T_ + t];
    int v = dv > 0 ? (int)dv : 0;

    // warp inclusive scan
    #pragma unroll
    for (int off = 1; off < 32; off <<= 1) {
        int n = __shfl_up_sync(0xffffffffu, v, off);
        if (lane >= off) v += n;
    }
    if (lane == 31) s_wsum[wid] = v;
    __syncthreads();
    if (wid == 0) {
        int wv = (lane < 16) ? s_wsum[lane] : 0;
        #pragma unroll
        for (int off = 1; off < 16; off <<= 1) {
            int n = __shfl_up_sync(0xffffffffu, wv, off);
            if (lane >= off) wv += n;
        }
        if (lane < 16) s_wsum[lane] = wv;
    }
    __syncthreads();
    if (wid > 0) v += s_wsum[wid - 1];
    s_csum[t] = v;
    __syncthreads();

    const int mel = s_csum[T_ - 1];

    // mel tail (one block per batch)
    if (s == 0 && t == 0) {
        const size_t total = (size_t)B_ * ML_ * C_;
        if (mel_mode == 1)      out[total + b] = (float)mel;
        else if (mel_mode == 2) ((long long*)(out + total))[b] = (long long)mel;
    }

    // inverse scatter restricted to this block's slice [p0, p1)
    const int p0 = s * SLC;
    const int p1 = p0 + SLC;
    int* gb = g_idx + b * ML_;

    {   // thread t owns input row t: fill [csum[t-1], csum[t]) ∩ [p0, p1)
        int start = (t == 0) ? 0 : s_csum[t - 1];
        int end   = s_csum[t];
        if (start < p0) start = p0;
        if (end   > p1) end   = p1;
        for (int p = start; p < end; ++p) gb[p] = t;
    }
    {   // masked tail within slice: [max(mel,p0), p1)
        int mstart = mel > p0 ? mel : p0;
        for (int p = mstart + t; p < p1; p += T_) gb[p] = -1;
    }
}

// ---------------------------------------------------------------------------
// Kernel 2: MLP-8 expand, bounded regs. grid = B_*ML_/RPB = 4096, block (96,4).
// ---------------------------------------------------------------------------
__global__ void __launch_bounds__(NTHR) lr_expand_kernel(const float4* __restrict__ x,
                                                         float4* __restrict__ out) {
    const int c4      = threadIdx.x;                   // 0..95
    const int ty      = threadIdx.y;                   // 0..3
    const int rowBase = blockIdx.x * RPB + ty;         // rows: rowBase + 4*k, k=0..7
    const int b       = (blockIdx.x * RPB) >> 12;      // batch (RPB | ML_)

    // 8 independent, warp-uniform idx loads upfront
    int idx[8];
    #pragma unroll
    for (int k = 0; k < 8; ++k)
        idx[k] = g_idx[rowBase + 4 * k];

    const float4* xb = x + (size_t)b * T_ * C4_;

    // two groups of {4 gathers -> 4 stores}: stores are issue-only, so group-2
    // loads overlap group-1 latency; only 4 float4 live at a time.
    #pragma unroll
    for (int g = 0; g < 2; ++g) {
        float4 v[4];
        #pragma unroll
        for (int k = 0; k < 4; ++k) {
            const int kk = g * 4 + k;
            if (idx[kk] >= 0) v[k] = __ldg(&xb[(size_t)idx[kk] * C4_ + c4]);
            else              v[k] = make_float4(0.f, 0.f, 0.f, 0.f);
        }
        #pragma unroll
        for (int k = 0; k < 4; ++k)
            out[(size_t)(rowBase + 4 * (g * 4 + k)) * C4_ + c4] = v[k];
    }
}

// ---------------------------------------------------------------------------
extern "C" void kernel_launch(void* const* d_in, const int* in_sizes, int n_in,
                              void* d_out, int out_size) {
    const float* x   = (const float*)d_in[0];
    const void*  dur = d_in[1];
    float* out = (float*)d_out;

    const long long total = (long long)B_ * ML_ * C_;
    const long long extra = (long long)out_size - total;
    int mel_mode = 0;
    if (extra == B_)          mel_mode = 1;   // float32 tail
    else if (extra == 2 * B_) mel_mode = 2;   // raw int64 tail

    lr_scan_kernel<<<B_ * SPB, T_>>>(dur, out, mel_mode);

    dim3 blk(C4_, 4);
    lr_expand_kernel<<<(B_ * ML_) / RPB, blk>>>((const float4*)x, (float4*)out);
}